// round 14
// baseline (speedup 1.0000x reference)
#include <cuda_runtime.h>

#define NN 50000
#define EE 800000
#define FMAX 128

static __constant__ float kNEG = 0.2f;
#define EPS_BN 1e-5f

// ---------------- scratch (device globals; no allocation allowed) ----------
__device__ float g_h[NN * FMAX];     // transformed features (fp32)
__device__ float g_fa[NN * FMAX];    // node feature ping
__device__ float g_fb[NN * FMAX];    // node feature pong
__device__ float g_es[NN * 4];
__device__ float g_ed[NN * 4];
__device__ int   g_deg[NN];          // invariant: zero at entry (self-cleaned)
__device__ int   g_rowptr[NN + 1];
__device__ int   g_cursor[NN];
__device__ int   g_adj[EE];
__device__ float g_bnstat[2 * FMAX]; // invariant: zero at entry (self-cleaned)
__device__ float g_Wf[FMAX * FMAX];  // BN-folded weight
__device__ float g_rvec[FMAX];       // BN-folded bias row
__device__ float g_va[2 * FMAX];     // W@a_src / W@a_dst for aggregate-first path
__device__ float g_scale[FMAX];      // precomputed BN scale (race-safe path)
__device__ float g_shift[FMAX];      // precomputed BN shift

// ---------------- CSR build (graph identical for all 5 layers) -------------
__global__ void hist_k(const int* __restrict__ dst, int* deg) {
    int e = blockIdx.x * 256 + threadIdx.x;
    if (e < EE) atomicAdd(&deg[dst[e]], 1);
}

// single-block exclusive scan; zeroes deg after use (self-clean)
__global__ void scan_k(int* __restrict__ deg, int* rowptr, int* cursor) {
    const int T = 1024;
    const int C = (NN + T - 1) / T;
    __shared__ int ssum[32];
    int t = threadIdx.x;
    int base = t * C;
    int s = 0;
#pragma unroll 8
    for (int i = 0; i < C; i++) {
        int idx = base + i;
        if (idx < NN) s += deg[idx];
    }
    int lane = t & 31, wid = t >> 5;
    int v = s;
    for (int o = 1; o < 32; o <<= 1) {
        int u = __shfl_up_sync(0xffffffffu, v, o);
        if (lane >= o) v += u;
    }
    if (lane == 31) ssum[wid] = v;
    __syncthreads();
    if (wid == 0) {
        int w = ssum[lane];
        for (int o = 1; o < 32; o <<= 1) {
            int u = __shfl_up_sync(0xffffffffu, w, o);
            if (lane >= o) w += u;
        }
        ssum[lane] = w;
    }
    __syncthreads();
    int excl = v - s + (wid ? ssum[wid - 1] : 0);
    int run = excl;
    for (int i = 0; i < C; i++) {
        int idx = base + i;
        if (idx < NN) {
            int dv = deg[idx];
            rowptr[idx] = run;
            cursor[idx] = run;
            run += dv;
            deg[idx] = 0;          // self-clean for next replay
        }
    }
    if (t == T - 1) rowptr[NN] = run;
}

__global__ void scatter_k(const int* __restrict__ src, const int* __restrict__ dst,
                          int* cursor, int* adj) {
    int e = blockIdx.x * 256 + threadIdx.x;
    if (e >= EE) return;
    int d = dst[e];
    int p = atomicAdd(&cursor[d], 1);
    adj[p] = src[e];
}

// ---------------- fused GEMM + attention epilogue ---------------------------
// h[N,K] = A[N,M] @ W[M,K] + rvec;  es/ed[n,hd] = h[n,hd,:] . a_{s,d}[hd,:]
// MINB: min blocks/SM hint (occupancy knob; K=128 GEMMs are latency-starved).
template <int M, int K, int H, int MINB>
__global__ void __launch_bounds__(256, MINB)
gemm2_k(const float* __restrict__ A, const float* __restrict__ W,
        const float* __restrict__ rvec,
        const float* __restrict__ avs, const float* __restrict__ avd,
        float* __restrict__ hout, float* __restrict__ es, float* __restrict__ ed) {
    constexpr int TX  = K / 4;          // 32 (K=128) or 8 (K=32)
    constexpr int TY  = 256 / TX;       // 8 or 32
    constexpr int D   = K / H;
    constexpr int G   = D / 4;          // lanes per head group (8 or 32)
    int tx = threadIdx.x, ty = threadIdx.y;
    int r0 = blockIdx.y * (TY * 4) + ty * 4;
    int c0 = tx * 4;

    long ab[4];
#pragma unroll
    for (int r = 0; r < 4; r++) ab[r] = (long)min(r0 + r, NN - 1) * M;

    float acc[4][4];
#pragma unroll
    for (int r = 0; r < 4; r++)
#pragma unroll
        for (int c = 0; c < 4; c++) acc[r][c] = 0.f;

#pragma unroll 2
    for (int m = 0; m < M; m += 4) {
        float4 av[4];
#pragma unroll
        for (int r = 0; r < 4; r++) av[r] = *(const float4*)&A[ab[r] + m];
#pragma unroll
        for (int mi = 0; mi < 4; mi++) {
            float4 t = *(const float4*)&W[(m + mi) * K + c0];
            float wq[4] = {t.x, t.y, t.z, t.w};
#pragma unroll
            for (int r = 0; r < 4; r++) {
                float am = ((const float*)&av[r])[mi];
#pragma unroll
                for (int c = 0; c < 4; c++)
                    acc[r][c] = fmaf(am, wq[c], acc[r][c]);
            }
        }
    }

    float rv[4], ws[4], wd[4];
#pragma unroll
    for (int c = 0; c < 4; c++) {
        rv[c] = rvec ? rvec[c0 + c] : 0.f;
        ws[c] = avs[c0 + c];
        wd[c] = avd[c0 + c];
    }

#pragma unroll
    for (int r = 0; r < 4; r++) {
        float hv[4];
        float pes = 0.f, ped = 0.f;
#pragma unroll
        for (int c = 0; c < 4; c++) {
            hv[c] = acc[r][c] + rv[c];
            pes = fmaf(hv[c], ws[c], pes);
            ped = fmaf(hv[c], wd[c], ped);
        }
        int row = r0 + r;
        if (row < NN)
            *(float4*)&hout[(long)row * K + c0] =
                make_float4(hv[0], hv[1], hv[2], hv[3]);
#pragma unroll
        for (int o = G / 2; o > 0; o >>= 1) {
            pes += __shfl_xor_sync(0xffffffffu, pes, o);
            ped += __shfl_xor_sync(0xffffffffu, ped, o);
        }
        if ((tx % G) == 0 && row < NN) {
            int head = c0 / D;
            es[row * H + head] = pes;
            ed[row * H + head] = ped;
        }
    }
}

// ---------------- fused gather: softmax-agg + self-loop + bias + relu -------
// one warp per dst node; accumulators in registers.
template <int F, int H>
__global__ void gat_gather_k(const int* __restrict__ rowptr, const int* __restrict__ adj,
                             const float* __restrict__ h, const float* __restrict__ es,
                             const float* __restrict__ ed, const float* __restrict__ bias,
                             float* __restrict__ out, int relu) {
    constexpr int VEC = F / 32;
    constexpr int D   = F / H;
    int w = (blockIdx.x * blockDim.x + threadIdx.x) >> 5;
    if (w >= NN) return;
    int lane = threadIdx.x & 31;
    int f0   = lane * VEC;
    int head = f0 / D;
    float edn = ed[w * H + head];
    float acc0 = 0.f, acc1 = 0.f, acc2 = 0.f, acc3 = 0.f;
    float den = 0.f;
    int beg = rowptr[w], end = rowptr[w + 1];
    for (int base = beg; base < end; base += 32) {
        int cnt  = min(32, end - base);
        int sreg = (base + lane < end) ? adj[base + lane] : 0;
#pragma unroll 4
        for (int j = 0; j < cnt; j++) {
            int s   = __shfl_sync(0xffffffffu, sreg, j);
            float a = es[s * H + head] + edn;
            a = a > 0.f ? a : kNEG * a;
            float ex = __expf(a);
            den += ex;
            const float* hp = h + (long)s * F + f0;
            if (VEC == 4) {
                float4 hv = *(const float4*)hp;
                acc0 = fmaf(ex, hv.x, acc0);
                acc1 = fmaf(ex, hv.y, acc1);
                acc2 = fmaf(ex, hv.z, acc2);
                acc3 = fmaf(ex, hv.w, acc3);
            } else {
                acc0 = fmaf(ex, hp[0], acc0);
            }
        }
    }
    {   // self loop
        float a = es[w * H + head] + edn;
        a = a > 0.f ? a : kNEG * a;
        float ex = __expf(a);
        den += ex;
        const float* hp = h + (long)w * F + f0;
        if (VEC == 4) {
            float4 hv = *(const float4*)hp;
            acc0 = fmaf(ex, hv.x, acc0);
            acc1 = fmaf(ex, hv.y, acc1);
            acc2 = fmaf(ex, hv.z, acc2);
            acc3 = fmaf(ex, hv.w, acc3);
        } else {
            acc0 = fmaf(ex, hp[0], acc0);
        }
    }
    float inv = 1.f / den;
    float* op = out + (long)w * F + f0;
    if (VEC == 4) {
        float4 o;
        o.x = acc0 * inv + bias[f0 + 0];
        o.y = acc1 * inv + bias[f0 + 1];
        o.z = acc2 * inv + bias[f0 + 2];
        o.w = acc3 * inv + bias[f0 + 3];
        if (relu) {
            o.x = fmaxf(o.x, 0.f); o.y = fmaxf(o.y, 0.f);
            o.z = fmaxf(o.z, 0.f); o.w = fmaxf(o.w, 0.f);
        }
        *(float4*)op = o;
    } else {
        float b = bias ? bias[f0] : 0.f;
        float o = acc0 * inv + b;
        if (relu) o = fmaxf(o, 0.f);
        op[0] = o;
    }
}

// ---------------- L5 aggregate-first helpers --------------------------------
__global__ void wa_k(const float* __restrict__ W, const float* __restrict__ as,
                     const float* __restrict__ ad, float* __restrict__ va) {
    int m = threadIdx.x;
    if (m >= 32) return;
    float s = 0.f, d = 0.f;
    for (int k = 0; k < 128; k += 4) {
        float4 w = *(const float4*)&W[m * 128 + k];
        float4 a1 = *(const float4*)&as[k];
        float4 a2 = *(const float4*)&ad[k];
        s = fmaf(w.x, a1.x, fmaf(w.y, a1.y, fmaf(w.z, a1.z, fmaf(w.w, a1.w, s))));
        d = fmaf(w.x, a2.x, fmaf(w.y, a2.y, fmaf(w.z, a2.z, fmaf(w.w, a2.w, d))));
    }
    va[m] = s;
    va[32 + m] = d;
}

// ---------------- batchnorm stats (g_bnstat is zero at entry) ---------------
__global__ void bn_part(const float* __restrict__ x, int F) {
    int t = threadIdx.x;                 // 128 threads
    int c = t % F;
    int sub = t / F;
    int step = 128 / F;
    int r0 = blockIdx.x * 128;
    int r1 = min(r0 + 128, NN);
    float s = 0.f, s2 = 0.f;
    for (int r = r0 + sub; r < r1; r += step) {
        float v = x[(long)r * F + c];
        s += v;
        s2 = fmaf(v, v, s2);
    }
    atomicAdd(&g_bnstat[c], s);
    atomicAdd(&g_bnstat[FMAX + c], s2);
}

// ---- fold BN into next layer's weight; 1 block -> self-clean is race-free --
__global__ void fold_k(const float* __restrict__ g, const float* __restrict__ be,
                       const float* __restrict__ W, float* __restrict__ Wout,
                       float* __restrict__ rvec, int M, int K) {
    __shared__ float sc[FMAX], sh[FMAX];
    int t = threadIdx.x;                 // 128 threads
    if (t < M) {
        float mu  = g_bnstat[t] * (1.f / NN);
        float var = g_bnstat[FMAX + t] * (1.f / NN) - mu * mu;
        float rs  = rsqrtf(var + EPS_BN);
        sc[t] = g[t] * rs;
        sh[t] = be[t] - mu * g[t] * rs;
        g_bnstat[t] = 0.f;               // self-clean (single block: safe)
        g_bnstat[FMAX + t] = 0.f;
    }
    __syncthreads();
    if (t < K) {
        float rv = 0.f;
        for (int m = 0; m < M; m++) {
            float w = W[m * K + t];
            Wout[m * K + t] = w * sc[m];
            rv = fmaf(sh[m], w, rv);
        }
        rvec[t] = rv;
    }
}

// ---- BN4 prep: compute scale/shift once, self-clean stats (1 block, safe) --
__global__ void bn_prep_k(const float* __restrict__ g, const float* __restrict__ be,
                          int F) {
    int t = threadIdx.x;
    if (t < F) {
        float mu  = g_bnstat[t] * (1.f / NN);
        float var = g_bnstat[FMAX + t] * (1.f / NN) - mu * mu;
        float rs  = rsqrtf(var + EPS_BN);
        g_scale[t] = g[t] * rs;
        g_shift[t] = be[t] - mu * g[t] * rs;
        g_bnstat[t] = 0.f;
        g_bnstat[FMAX + t] = 0.f;
    }
}

// ---- fused BN apply + relu + L5 attention logits (warp-per-row, F=32) ------
__global__ void bn_attn_k(float* __restrict__ x, const float* __restrict__ va,
                          float* __restrict__ es, float* __restrict__ ed) {
    int w = (blockIdx.x * blockDim.x + threadIdx.x) >> 5;
    if (w >= NN) return;
    int lane = threadIdx.x & 31;
    long i = (long)w * 32 + lane;
    float v = x[i] * g_scale[lane] + g_shift[lane];
    v = fmaxf(v, 0.f);                    // relu
    x[i] = v;
    float s = v * va[lane];
    float d = v * va[32 + lane];
#pragma unroll
    for (int o = 16; o > 0; o >>= 1) {
        s += __shfl_xor_sync(0xffffffffu, s, o);
        d += __shfl_xor_sync(0xffffffffu, d, o);
    }
    if (lane == 0) { es[w] = s; ed[w] = d; }
}

// ---------------- host driver ----------------------------------------------
extern "C" void kernel_launch(void* const* d_in, const int* in_sizes, int n_in,
                              void* d_out, int out_size) {
    const float* x   = (const float*)d_in[0];
    const int*   ei  = (const int*)d_in[1];
    const int*   src = ei;
    const int*   dst = ei + EE;
    const float* W1 = (const float*)d_in[2],  *as1 = (const float*)d_in[3],
               * ad1 = (const float*)d_in[4], *b1  = (const float*)d_in[5],
               * g1  = (const float*)d_in[6], *be1 = (const float*)d_in[7];
    const float* W2 = (const float*)d_in[8],  *as2 = (const float*)d_in[9],
               * ad2 = (const float*)d_in[10], *b2  = (const float*)d_in[11],
               * g2  = (const float*)d_in[12], *be2 = (const float*)d_in[13];
    const float* W3 = (const float*)d_in[14], *as3 = (const float*)d_in[15],
               * ad3 = (const float*)d_in[16], *b3  = (const float*)d_in[17];
    const float* W4 = (const float*)d_in[18], *as4 = (const float*)d_in[19],
               * ad4 = (const float*)d_in[20], *b4  = (const float*)d_in[21],
               * g4  = (const float*)d_in[22], *be4 = (const float*)d_in[23];
    const float* W5 = (const float*)d_in[24], *as5 = (const float*)d_in[25],
               * ad5 = (const float*)d_in[26], *b5  = (const float*)d_in[27];

    float *h, *fa, *fb, *es, *ed, *Wf, *rv, *va;
    int *deg, *rowptr, *cursor, *adj;
    cudaGetSymbolAddress((void**)&h,      g_h);
    cudaGetSymbolAddress((void**)&fa,     g_fa);
    cudaGetSymbolAddress((void**)&fb,     g_fb);
    cudaGetSymbolAddress((void**)&es,     g_es);
    cudaGetSymbolAddress((void**)&ed,     g_ed);
    cudaGetSymbolAddress((void**)&deg,    g_deg);
    cudaGetSymbolAddress((void**)&rowptr, g_rowptr);
    cudaGetSymbolAddress((void**)&cursor, g_cursor);
    cudaGetSymbolAddress((void**)&adj,    g_adj);
    cudaGetSymbolAddress((void**)&Wf,     g_Wf);
    cudaGetSymbolAddress((void**)&rv,     g_rvec);
    cudaGetSymbolAddress((void**)&va,     g_va);

    // one-time side stream + fork/join events (host objects, not device mem)
    static cudaStream_t s2 = nullptr;
    static cudaEvent_t evF = nullptr, evJ = nullptr;
    if (!s2) {
        cudaStreamCreateWithFlags(&s2, cudaStreamNonBlocking);
        cudaEventCreateWithFlags(&evF, cudaEventDisableTiming);
        cudaEventCreateWithFlags(&evJ, cudaEventDisableTiming);
    }

    const dim3 GB128(32, 8), GB32(8, 32);
    const dim3 GGL(1, (NN + 31) / 32);    // K=128 geometry: 32 rows/block
    const dim3 GGS(1, (NN + 127) / 128);  // K=32 geometry: 128 rows/block
    const int  GBLK = (NN * 32 + 255) / 256;

    // ---- CSR build + wa on side stream, overlapped with L1 GEMM ----
    cudaEventRecord(evF, 0);
    cudaStreamWaitEvent(s2, evF, 0);
    hist_k<<<(EE + 255) / 256, 256, 0, s2>>>(dst, deg);
    wa_k<<<1, 32, 0, s2>>>(W5, as5, ad5, va);          // depends only on inputs
    scan_k<<<1, 1024, 0, s2>>>(deg, rowptr, cursor);
    scatter_k<<<(EE + 255) / 256, 256, 0, s2>>>(src, dst, cursor, adj);
    cudaEventRecord(evJ, s2);

    // ---- L1: GAT(128 -> 128, H=4) ----
    gemm2_k<128, 128, 4, 5><<<GGL, GB128>>>(x, W1, nullptr, as1, ad1, h, es, ed);
    cudaStreamWaitEvent(0, evJ, 0);      // join: gather needs CSR
    gat_gather_k<128, 4><<<GBLK, 256>>>(rowptr, adj, h, es, ed, b1, fa, 1);

    // ---- BN1 stats + fold into L2 ----
    bn_part<<<(NN + 127) / 128, 128>>>(fa, 128);
    fold_k<<<1, 128>>>(g1, be1, W2, Wf, rv, 128, 128);

    // ---- L2: GAT(128 -> 128, H=4) ----
    gemm2_k<128, 128, 4, 5><<<GGL, GB128>>>(fa, Wf, rv, as2, ad2, h, es, ed);
    gat_gather_k<128, 4><<<GBLK, 256>>>(rowptr, adj, h, es, ed, b2, fb, 1);

    // ---- BN2 stats + fold into L3 ----
    bn_part<<<(NN + 127) / 128, 128>>>(fb, 128);
    fold_k<<<1, 128>>>(g2, be2, W3, Wf, rv, 128, 32);

    // ---- L3: GAT(128 -> 32, H=1) ----
    gemm2_k<128, 32, 1, 1><<<GGS, GB32>>>(fb, Wf, rv, as3, ad3, h, es, ed);
    gat_gather_k<32, 1><<<GBLK, 256>>>(rowptr, adj, h, es, ed, b3, fa, 1);

    // ---- L4: GAT(32 -> 32, H=1) ----
    gemm2_k<32, 32, 1, 1><<<GGS, GB32>>>(fa, W4, nullptr, as4, ad4, h, es, ed);
    gat_gather_k<32, 1><<<GBLK, 256>>>(rowptr, adj, h, es, ed, b4, fb, 1);

    // ---- BN4 stats + prep; fused apply+relu+L5 attention logits ----
    bn_part<<<(NN + 127) / 128, 128>>>(fb, 32);
    bn_prep_k<<<1, 128>>>(g4, be4, 32);
    bn_attn_k<<<GBLK, 256>>>(fb, va, es, ed);

    // ---- L5: GAT(32 -> 128, H=1), aggregate-first ----
    gat_gather_k<32, 1><<<GBLK, 256>>>(rowptr, adj, fb, es, ed, nullptr, fa, 0);
    gemm2_k<32, 128, 1, 5><<<GGL, GB128>>>(fa, W5, b5, as5, ad5, (float*)d_out, es, ed);
}

// round 15
// speedup vs baseline: 1.2586x; 1.2586x over previous
#include <cuda_runtime.h>

#define NN 50000
#define EE 800000
#define FMAX 128

static __constant__ float kNEG = 0.2f;
#define EPS_BN 1e-5f

// ---------------- scratch (device globals; no allocation allowed) ----------
__device__ float g_h[NN * FMAX];     // transformed features (fp32)
__device__ float g_fa[NN * FMAX];    // node feature ping
__device__ float g_fb[NN * FMAX];    // node feature pong
__device__ float g_es[NN * 4];
__device__ float g_ed[NN * 4];
__device__ int   g_deg[NN];          // invariant: zero at entry (self-cleaned)
__device__ int   g_rowptr[NN + 1];
__device__ int   g_cursor[NN];
__device__ int   g_adj[EE];
__device__ float g_bnstat[2 * FMAX]; // invariant: zero at entry (self-cleaned)
__device__ float g_Wf[FMAX * FMAX];  // BN-folded weight
__device__ float g_rvec[FMAX];       // BN-folded bias row
__device__ float g_va[2 * FMAX];     // W@a_src / W@a_dst for aggregate-first path
__device__ float g_scale[FMAX];      // precomputed BN scale (race-safe path)
__device__ float g_shift[FMAX];      // precomputed BN shift

// ---------------- CSR build (graph identical for all 5 layers) -------------
__global__ void hist_k(const int* __restrict__ dst, int* deg) {
    int e = blockIdx.x * 256 + threadIdx.x;
    if (e < EE) atomicAdd(&deg[dst[e]], 1);
}

// single-block exclusive scan; zeroes deg after use (self-clean)
__global__ void scan_k(int* __restrict__ deg, int* rowptr, int* cursor) {
    const int T = 1024;
    const int C = (NN + T - 1) / T;
    __shared__ int ssum[32];
    int t = threadIdx.x;
    int base = t * C;
    int s = 0;
#pragma unroll 8
    for (int i = 0; i < C; i++) {
        int idx = base + i;
        if (idx < NN) s += deg[idx];
    }
    int lane = t & 31, wid = t >> 5;
    int v = s;
    for (int o = 1; o < 32; o <<= 1) {
        int u = __shfl_up_sync(0xffffffffu, v, o);
        if (lane >= o) v += u;
    }
    if (lane == 31) ssum[wid] = v;
    __syncthreads();
    if (wid == 0) {
        int w = ssum[lane];
        for (int o = 1; o < 32; o <<= 1) {
            int u = __shfl_up_sync(0xffffffffu, w, o);
            if (lane >= o) w += u;
        }
        ssum[lane] = w;
    }
    __syncthreads();
    int excl = v - s + (wid ? ssum[wid - 1] : 0);
    int run = excl;
    for (int i = 0; i < C; i++) {
        int idx = base + i;
        if (idx < NN) {
            int dv = deg[idx];
            rowptr[idx] = run;
            cursor[idx] = run;
            run += dv;
            deg[idx] = 0;          // self-clean for next replay
        }
    }
    if (t == T - 1) rowptr[NN] = run;
}

__global__ void scatter_k(const int* __restrict__ src, const int* __restrict__ dst,
                          int* cursor, int* adj) {
    int e = blockIdx.x * 256 + threadIdx.x;
    if (e >= EE) return;
    int d = dst[e];
    int p = atomicAdd(&cursor[d], 1);
    adj[p] = src[e];
}

// ---------------- fused GEMM + attention epilogue ---------------------------
// h[N,K] = A[N,M] @ W[M,K] + rvec;  es/ed[n,hd] = h[n,hd,:] . a_{s,d}[hd,:]
// regs=64 / occ~45% is the measured optimum; do NOT constrain min-blocks
// (launch_bounds(256,5) forced 48 regs -> spills -> +117us, R14).
template <int M, int K, int H>
__global__ void __launch_bounds__(256)
gemm2_k(const float* __restrict__ A, const float* __restrict__ W,
        const float* __restrict__ rvec,
        const float* __restrict__ avs, const float* __restrict__ avd,
        float* __restrict__ hout, float* __restrict__ es, float* __restrict__ ed) {
    constexpr int TX  = K / 4;          // 32 (K=128) or 8 (K=32)
    constexpr int TY  = 256 / TX;       // 8 or 32
    constexpr int D   = K / H;
    constexpr int G   = D / 4;          // lanes per head group (8 or 32)
    int tx = threadIdx.x, ty = threadIdx.y;
    int r0 = blockIdx.y * (TY * 4) + ty * 4;
    int c0 = tx * 4;

    long ab[4];
#pragma unroll
    for (int r = 0; r < 4; r++) ab[r] = (long)min(r0 + r, NN - 1) * M;

    float acc[4][4];
#pragma unroll
    for (int r = 0; r < 4; r++)
#pragma unroll
        for (int c = 0; c < 4; c++) acc[r][c] = 0.f;

#pragma unroll 2
    for (int m = 0; m < M; m += 4) {
        float4 av[4];
#pragma unroll
        for (int r = 0; r < 4; r++) av[r] = *(const float4*)&A[ab[r] + m];
#pragma unroll
        for (int mi = 0; mi < 4; mi++) {
            float4 t = *(const float4*)&W[(m + mi) * K + c0];
            float wq[4] = {t.x, t.y, t.z, t.w};
#pragma unroll
            for (int r = 0; r < 4; r++) {
                float am = ((const float*)&av[r])[mi];
#pragma unroll
                for (int c = 0; c < 4; c++)
                    acc[r][c] = fmaf(am, wq[c], acc[r][c]);
            }
        }
    }

    float rv[4], ws[4], wd[4];
#pragma unroll
    for (int c = 0; c < 4; c++) {
        rv[c] = rvec ? rvec[c0 + c] : 0.f;
        ws[c] = avs[c0 + c];
        wd[c] = avd[c0 + c];
    }

#pragma unroll
    for (int r = 0; r < 4; r++) {
        float hv[4];
        float pes = 0.f, ped = 0.f;
#pragma unroll
        for (int c = 0; c < 4; c++) {
            hv[c] = acc[r][c] + rv[c];
            pes = fmaf(hv[c], ws[c], pes);
            ped = fmaf(hv[c], wd[c], ped);
        }
        int row = r0 + r;
        if (row < NN)
            *(float4*)&hout[(long)row * K + c0] =
                make_float4(hv[0], hv[1], hv[2], hv[3]);
#pragma unroll
        for (int o = G / 2; o > 0; o >>= 1) {
            pes += __shfl_xor_sync(0xffffffffu, pes, o);
            ped += __shfl_xor_sync(0xffffffffu, ped, o);
        }
        if ((tx % G) == 0 && row < NN) {
            int head = c0 / D;
            es[row * H + head] = pes;
            ed[row * H + head] = ped;
        }
    }
}

// ---------------- fused gather: softmax-agg + self-loop + bias + relu -------
// one warp per dst node; accumulators in registers.
template <int F, int H>
__global__ void gat_gather_k(const int* __restrict__ rowptr, const int* __restrict__ adj,
                             const float* __restrict__ h, const float* __restrict__ es,
                             const float* __restrict__ ed, const float* __restrict__ bias,
                             float* __restrict__ out, int relu) {
    constexpr int VEC = F / 32;
    constexpr int D   = F / H;
    int w = (blockIdx.x * blockDim.x + threadIdx.x) >> 5;
    if (w >= NN) return;
    int lane = threadIdx.x & 31;
    int f0   = lane * VEC;
    int head = f0 / D;
    float edn = ed[w * H + head];
    float acc0 = 0.f, acc1 = 0.f, acc2 = 0.f, acc3 = 0.f;
    float den = 0.f;
    int beg = rowptr[w], end = rowptr[w + 1];
    for (int base = beg; base < end; base += 32) {
        int cnt  = min(32, end - base);
        int sreg = (base + lane < end) ? adj[base + lane] : 0;
#pragma unroll 4
        for (int j = 0; j < cnt; j++) {
            int s   = __shfl_sync(0xffffffffu, sreg, j);
            float a = es[s * H + head] + edn;
            a = a > 0.f ? a : kNEG * a;
            float ex = __expf(a);
            den += ex;
            const float* hp = h + (long)s * F + f0;
            if (VEC == 4) {
                float4 hv = *(const float4*)hp;
                acc0 = fmaf(ex, hv.x, acc0);
                acc1 = fmaf(ex, hv.y, acc1);
                acc2 = fmaf(ex, hv.z, acc2);
                acc3 = fmaf(ex, hv.w, acc3);
            } else {
                acc0 = fmaf(ex, hp[0], acc0);
            }
        }
    }
    {   // self loop
        float a = es[w * H + head] + edn;
        a = a > 0.f ? a : kNEG * a;
        float ex = __expf(a);
        den += ex;
        const float* hp = h + (long)w * F + f0;
        if (VEC == 4) {
            float4 hv = *(const float4*)hp;
            acc0 = fmaf(ex, hv.x, acc0);
            acc1 = fmaf(ex, hv.y, acc1);
            acc2 = fmaf(ex, hv.z, acc2);
            acc3 = fmaf(ex, hv.w, acc3);
        } else {
            acc0 = fmaf(ex, hp[0], acc0);
        }
    }
    float inv = 1.f / den;
    float* op = out + (long)w * F + f0;
    if (VEC == 4) {
        float4 o;
        o.x = acc0 * inv + bias[f0 + 0];
        o.y = acc1 * inv + bias[f0 + 1];
        o.z = acc2 * inv + bias[f0 + 2];
        o.w = acc3 * inv + bias[f0 + 3];
        if (relu) {
            o.x = fmaxf(o.x, 0.f); o.y = fmaxf(o.y, 0.f);
            o.z = fmaxf(o.z, 0.f); o.w = fmaxf(o.w, 0.f);
        }
        *(float4*)op = o;
    } else {
        float b = bias ? bias[f0] : 0.f;
        float o = acc0 * inv + b;
        if (relu) o = fmaxf(o, 0.f);
        op[0] = o;
    }
}

// ---------------- L5 aggregate-first helpers --------------------------------
__global__ void wa_k(const float* __restrict__ W, const float* __restrict__ as,
                     const float* __restrict__ ad, float* __restrict__ va) {
    int m = threadIdx.x;
    if (m >= 32) return;
    float s = 0.f, d = 0.f;
    for (int k = 0; k < 128; k += 4) {
        float4 w = *(const float4*)&W[m * 128 + k];
        float4 a1 = *(const float4*)&as[k];
        float4 a2 = *(const float4*)&ad[k];
        s = fmaf(w.x, a1.x, fmaf(w.y, a1.y, fmaf(w.z, a1.z, fmaf(w.w, a1.w, s))));
        d = fmaf(w.x, a2.x, fmaf(w.y, a2.y, fmaf(w.z, a2.z, fmaf(w.w, a2.w, d))));
    }
    va[m] = s;
    va[32 + m] = d;
}

// ---------------- batchnorm stats (g_bnstat is zero at entry) ---------------
__global__ void bn_part(const float* __restrict__ x, int F) {
    int t = threadIdx.x;                 // 128 threads
    int c = t % F;
    int sub = t / F;
    int step = 128 / F;
    int r0 = blockIdx.x * 128;
    int r1 = min(r0 + 128, NN);
    float s = 0.f, s2 = 0.f;
    for (int r = r0 + sub; r < r1; r += step) {
        float v = x[(long)r * F + c];
        s += v;
        s2 = fmaf(v, v, s2);
    }
    atomicAdd(&g_bnstat[c], s);
    atomicAdd(&g_bnstat[FMAX + c], s2);
}

// ---- fold BN into next layer's weight; 1 block -> self-clean is race-free --
__global__ void fold_k(const float* __restrict__ g, const float* __restrict__ be,
                       const float* __restrict__ W, float* __restrict__ Wout,
                       float* __restrict__ rvec, int M, int K) {
    __shared__ float sc[FMAX], sh[FMAX];
    int t = threadIdx.x;                 // 128 threads
    if (t < M) {
        float mu  = g_bnstat[t] * (1.f / NN);
        float var = g_bnstat[FMAX + t] * (1.f / NN) - mu * mu;
        float rs  = rsqrtf(var + EPS_BN);
        sc[t] = g[t] * rs;
        sh[t] = be[t] - mu * g[t] * rs;
        g_bnstat[t] = 0.f;               // self-clean (single block: safe)
        g_bnstat[FMAX + t] = 0.f;
    }
    __syncthreads();
    if (t < K) {
        float rv = 0.f;
        for (int m = 0; m < M; m++) {
            float w = W[m * K + t];
            Wout[m * K + t] = w * sc[m];
            rv = fmaf(sh[m], w, rv);
        }
        rvec[t] = rv;
    }
}

// ---- BN4 prep: compute scale/shift once, self-clean stats (1 block, safe) --
__global__ void bn_prep_k(const float* __restrict__ g, const float* __restrict__ be,
                          int F) {
    int t = threadIdx.x;
    if (t < F) {
        float mu  = g_bnstat[t] * (1.f / NN);
        float var = g_bnstat[FMAX + t] * (1.f / NN) - mu * mu;
        float rs  = rsqrtf(var + EPS_BN);
        g_scale[t] = g[t] * rs;
        g_shift[t] = be[t] - mu * g[t] * rs;
        g_bnstat[t] = 0.f;
        g_bnstat[FMAX + t] = 0.f;
    }
}

// ---- fused BN apply + relu + L5 attention logits (warp-per-row, F=32) ------
__global__ void bn_attn_k(float* __restrict__ x, const float* __restrict__ va,
                          float* __restrict__ es, float* __restrict__ ed) {
    int w = (blockIdx.x * blockDim.x + threadIdx.x) >> 5;
    if (w >= NN) return;
    int lane = threadIdx.x & 31;
    long i = (long)w * 32 + lane;
    float v = x[i] * g_scale[lane] + g_shift[lane];
    v = fmaxf(v, 0.f);                    // relu
    x[i] = v;
    float s = v * va[lane];
    float d = v * va[32 + lane];
#pragma unroll
    for (int o = 16; o > 0; o >>= 1) {
        s += __shfl_xor_sync(0xffffffffu, s, o);
        d += __shfl_xor_sync(0xffffffffu, d, o);
    }
    if (lane == 0) { es[w] = s; ed[w] = d; }
}

// ---------------- host driver ----------------------------------------------
extern "C" void kernel_launch(void* const* d_in, const int* in_sizes, int n_in,
                              void* d_out, int out_size) {
    const float* x   = (const float*)d_in[0];
    const int*   ei  = (const int*)d_in[1];
    const int*   src = ei;
    const int*   dst = ei + EE;
    const float* W1 = (const float*)d_in[2],  *as1 = (const float*)d_in[3],
               * ad1 = (const float*)d_in[4], *b1  = (const float*)d_in[5],
               * g1  = (const float*)d_in[6], *be1 = (const float*)d_in[7];
    const float* W2 = (const float*)d_in[8],  *as2 = (const float*)d_in[9],
               * ad2 = (const float*)d_in[10], *b2  = (const float*)d_in[11],
               * g2  = (const float*)d_in[12], *be2 = (const float*)d_in[13];
    const float* W3 = (const float*)d_in[14], *as3 = (const float*)d_in[15],
               * ad3 = (const float*)d_in[16], *b3  = (const float*)d_in[17];
    const float* W4 = (const float*)d_in[18], *as4 = (const float*)d_in[19],
               * ad4 = (const float*)d_in[20], *b4  = (const float*)d_in[21],
               * g4  = (const float*)d_in[22], *be4 = (const float*)d_in[23];
    const float* W5 = (const float*)d_in[24], *as5 = (const float*)d_in[25],
               * ad5 = (const float*)d_in[26], *b5  = (const float*)d_in[27];

    float *h, *fa, *fb, *es, *ed, *Wf, *rv, *va;
    int *deg, *rowptr, *cursor, *adj;
    cudaGetSymbolAddress((void**)&h,      g_h);
    cudaGetSymbolAddress((void**)&fa,     g_fa);
    cudaGetSymbolAddress((void**)&fb,     g_fb);
    cudaGetSymbolAddress((void**)&es,     g_es);
    cudaGetSymbolAddress((void**)&ed,     g_ed);
    cudaGetSymbolAddress((void**)&deg,    g_deg);
    cudaGetSymbolAddress((void**)&rowptr, g_rowptr);
    cudaGetSymbolAddress((void**)&cursor, g_cursor);
    cudaGetSymbolAddress((void**)&adj,    g_adj);
    cudaGetSymbolAddress((void**)&Wf,     g_Wf);
    cudaGetSymbolAddress((void**)&rv,     g_rvec);
    cudaGetSymbolAddress((void**)&va,     g_va);

    // one-time side stream + fork/join events (host objects, not device mem)
    static cudaStream_t s2 = nullptr;
    static cudaEvent_t evF = nullptr, evJ = nullptr;
    if (!s2) {
        cudaStreamCreateWithFlags(&s2, cudaStreamNonBlocking);
        cudaEventCreateWithFlags(&evF, cudaEventDisableTiming);
        cudaEventCreateWithFlags(&evJ, cudaEventDisableTiming);
    }

    const dim3 GB128(32, 8), GB32(8, 32);
    const dim3 GGL(1, (NN + 31) / 32);    // K=128 geometry: 32 rows/block
    const dim3 GGS(1, (NN + 127) / 128);  // K=32 geometry: 128 rows/block
    const int  GBLK = (NN * 32 + 255) / 256;

    // ---- CSR build + wa on side stream, overlapped with L1 GEMM ----
    cudaEventRecord(evF, 0);
    cudaStreamWaitEvent(s2, evF, 0);
    hist_k<<<(EE + 255) / 256, 256, 0, s2>>>(dst, deg);
    wa_k<<<1, 32, 0, s2>>>(W5, as5, ad5, va);          // depends only on inputs
    scan_k<<<1, 1024, 0, s2>>>(deg, rowptr, cursor);
    scatter_k<<<(EE + 255) / 256, 256, 0, s2>>>(src, dst, cursor, adj);
    cudaEventRecord(evJ, s2);

    // ---- L1: GAT(128 -> 128, H=4) ----
    gemm2_k<128, 128, 4><<<GGL, GB128>>>(x, W1, nullptr, as1, ad1, h, es, ed);
    cudaStreamWaitEvent(0, evJ, 0);      // join: gather needs CSR
    gat_gather_k<128, 4><<<GBLK, 256>>>(rowptr, adj, h, es, ed, b1, fa, 1);

    // ---- BN1 stats + fold into L2 ----
    bn_part<<<(NN + 127) / 128, 128>>>(fa, 128);
    fold_k<<<1, 128>>>(g1, be1, W2, Wf, rv, 128, 128);

    // ---- L2: GAT(128 -> 128, H=4) ----
    gemm2_k<128, 128, 4><<<GGL, GB128>>>(fa, Wf, rv, as2, ad2, h, es, ed);
    gat_gather_k<128, 4><<<GBLK, 256>>>(rowptr, adj, h, es, ed, b2, fb, 1);

    // ---- BN2 stats + fold into L3 ----
    bn_part<<<(NN + 127) / 128, 128>>>(fb, 128);
    fold_k<<<1, 128>>>(g2, be2, W3, Wf, rv, 128, 32);

    // ---- L3: GAT(128 -> 32, H=1) ----
    gemm2_k<128, 32, 1><<<GGS, GB32>>>(fb, Wf, rv, as3, ad3, h, es, ed);
    gat_gather_k<32, 1><<<GBLK, 256>>>(rowptr, adj, h, es, ed, b3, fa, 1);

    // ---- L4: GAT(32 -> 32, H=1) ----
    gemm2_k<32, 32, 1><<<GGS, GB32>>>(fa, W4, nullptr, as4, ad4, h, es, ed);
    gat_gather_k<32, 1><<<GBLK, 256>>>(rowptr, adj, h, es, ed, b4, fb, 1);

    // ---- BN4 stats + prep; fused apply+relu+L5 attention logits ----
    bn_part<<<(NN + 127) / 128, 128>>>(fb, 32);
    bn_prep_k<<<1, 128>>>(g4, be4, 32);
    bn_attn_k<<<GBLK, 256>>>(fb, va, es, ed);

    // ---- L5: GAT(32 -> 128, H=1), aggregate-first ----
    gat_gather_k<32, 1><<<GBLK, 256>>>(rowptr, adj, fb, es, ed, nullptr, fa, 0);
    gemm2_k<32, 128, 1><<<GGL, GB128>>>(fa, W5, b5, as5, ad5, (float*)d_out, es, ed);
}